// round 16
// baseline (speedup 1.0000x reference)
#include <cuda_runtime.h>
#include <cuda_fp16.h>
#include <cstdint>

// ---------------------------------------------------------------------------
// Problem constants
// ---------------------------------------------------------------------------
#define N_IMG   16
#define C_IN    64
#define C_OUT   64
#define HH      128
#define WW      128
#define W_ELEMS (C_OUT * C_IN * 9)      // 36864

// ---------------------------------------------------------------------------
// Persistent device scratch
// ---------------------------------------------------------------------------
__device__ __half  g_wB[9 * 64 * 64];     // [tap][oc][c] fp16 fused weights
__device__ float   g_beff[C_OUT];

// ---------------------------------------------------------------------------
// PTX helpers (sm_103-baseline: cp.async, ldmatrix, mma.sync)
// ---------------------------------------------------------------------------
__device__ __forceinline__ uint32_t smem_to_u32(const void* p) {
    uint32_t a;
    asm("{ .reg .u64 t; cvta.to.shared.u64 t, %1; cvt.u32.u64 %0, t; }"
        : "=r"(a) : "l"(p));
    return a;
}
__device__ __forceinline__ void cp16(uint32_t dst, const void* src) {
    asm volatile("cp.async.cg.shared.global [%0], [%1], 16;" :: "r"(dst), "l"(src));
}
__device__ __forceinline__ void cp_commit() {
    asm volatile("cp.async.commit_group;" ::: "memory");
}
__device__ __forceinline__ void cp_wait0() {
    asm volatile("cp.async.wait_group 0;" ::: "memory");
}
__device__ __forceinline__ void ldsm_x4(uint32_t* r, uint32_t addr) {
    asm volatile("ldmatrix.sync.aligned.m8n8.x4.shared.b16 {%0,%1,%2,%3}, [%4];"
        : "=r"(r[0]), "=r"(r[1]), "=r"(r[2]), "=r"(r[3]) : "r"(addr));
}
__device__ __forceinline__ void mma16816(float* d, const uint32_t* a, const uint32_t* b) {
    asm volatile(
        "mma.sync.aligned.m16n8k16.row.col.f32.f16.f16.f32 "
        "{%0,%1,%2,%3}, {%4,%5,%6,%7}, {%8,%9}, {%0,%1,%2,%3};"
        : "+f"(d[0]), "+f"(d[1]), "+f"(d[2]), "+f"(d[3])
        : "r"(a[0]), "r"(a[1]), "r"(a[2]), "r"(a[3]), "r"(b[0]), "r"(b[1]));
}
__device__ __forceinline__ float4 ldg_cs_f4(const float* p) {
    float4 v;
    asm volatile("ld.global.cs.v4.f32 {%0,%1,%2,%3}, [%4];"
        : "=f"(v.x), "=f"(v.y), "=f"(v.z), "=f"(v.w) : "l"(p));
    return v;
}
__device__ __forceinline__ void sts128(uint32_t addr, uint32_t r0, uint32_t r1,
                                       uint32_t r2, uint32_t r3) {
    asm volatile("st.shared.v4.b32 [%0], {%1,%2,%3,%4};"
        :: "r"(addr), "r"(r0), "r"(r1), "r"(r2), "r"(r3) : "memory");
}
__device__ __forceinline__ uint32_t packh2(float a, float b) {
    __half2 h = __floats2half2_rn(a, b);     // lo=a, hi=b
    return *reinterpret_cast<uint32_t*>(&h);
}

// ---------------------------------------------------------------------------
// Kernel 1: fused scale + weight prep (single launch).
//   Every block redundantly computes both |w| sums with an IDENTICAL fp32
//   instruction sequence (16 rotating accumulators per tensor -> fixed fp32
//   tree fold -> fp64 shared tree) => bitwise-identical scales in all blocks.
//   Then each block quantizes+fuses its 576-element slice of the weights.
// ---------------------------------------------------------------------------
__global__ __launch_bounds__(256)
void prep_all_kernel(const float* __restrict__ w,
                     const float* __restrict__ b,
                     const float* __restrict__ wc,
                     const float* __restrict__ bc,
                     const float* __restrict__ gate) {
    const int tid = threadIdx.x;
    __shared__ double red[256];
    __shared__ float ssc[2];

    // --- phase 1: both |.| sums in one load pass ---
    float accw[16], accc[16];
#pragma unroll
    for (int j = 0; j < 16; ++j) { accw[j] = 0.0f; accc[j] = 0.0f; }
    const float4* w4  = reinterpret_cast<const float4*>(w);
    const float4* wc4 = reinterpret_cast<const float4*>(wc);
    int it = 0;
    for (int i4 = tid; i4 < W_ELEMS / 4; i4 += 256, ++it) {   // 36 iters
        float4 v = w4[i4];
        float4 u = wc4[i4];
        int j = (it & 3) * 4;
        accw[j + 0] += fabsf(v.x); accw[j + 1] += fabsf(v.y);
        accw[j + 2] += fabsf(v.z); accw[j + 3] += fabsf(v.w);
        accc[j + 0] += fabsf(u.x); accc[j + 1] += fabsf(u.y);
        accc[j + 2] += fabsf(u.z); accc[j + 3] += fabsf(u.w);
    }
    // fixed fp32 tree fold (same order every block/thread)
#pragma unroll
    for (int st = 8; st >= 1; st >>= 1)
#pragma unroll
        for (int j = 0; j < 8; ++j)
            if (j < st) { accw[j] += accw[j + st]; accc[j] += accc[j + st]; }

    // fp64 shared tree reduce, tensor 0 then tensor 1
#pragma unroll 1
    for (int t = 0; t < 2; ++t) {
        red[tid] = (double)(t == 0 ? accw[0] : accc[0]);
        __syncthreads();
        for (int off = 128; off > 0; off >>= 1) {
            if (tid < off) red[tid] += red[tid + off];
            __syncthreads();
        }
        if (tid == 0)
            ssc[t] = fmaxf((float)(red[0] / (double)W_ELEMS), 1e-5f);
        __syncthreads();
    }

    // --- phase 2: quantize+fuse this block's 576-element slice ---
    const float s1 = ssc[0], s2 = ssc[1];
    const float g = 1.0f / (1.0f + expf(-gate[0]));
    const int base = blockIdx.x * 576;
    for (int i = base + tid; i < base + 576; i += 256) {
        float q1 = fminf(fmaxf(rintf(w[i]  / s1), -1.0f), 1.0f) * s1;
        float q2 = fminf(fmaxf(rintf(wc[i] / s2), -1.0f), 1.0f) * s2;
        int o = i / (C_IN * 9);
        int r = i - o * (C_IN * 9);
        int c = r / 9;
        int k = r - c * 9;
        g_wB[k * 4096 + o * 64 + c] = __float2half_rn(q1 + g * q2);
    }
    if (blockIdx.x == 0 && tid < C_OUT)
        g_beff[tid] = b[tid] + g * bc[tid];
}

// ---------------------------------------------------------------------------
// Kernel 2: persistent implicit-GEMM conv via HMMA with FUSED transpose
//   (byte-identical to the 71.8us round-14 winner).
// SMEM: B [0,73728) | A ring 8 x 16640 [73728, 206848)
// ---------------------------------------------------------------------------
#define AROW_B   16640              // 130*128
#define A_OFF    73728
#define SMEM_CONV 206848
#define NTILES2  1024               // 16 images * 64 row-pairs
#define NCTA     148

__device__ __forceinline__ bool ldg_row(float4* v, const float* __restrict__ x,
                                        int n, int pr, int w, int l) {
    int gy = pr - 1;
    bool valid = (gy >= 0) && (gy < HH);
    if (valid) {
        const float* rowp = x + ((size_t)(n * 64 + 8 * w) * HH + gy) * WW + 4 * l;
#pragma unroll
        for (int k = 0; k < 8; ++k)
            v[k] = ldg_cs_f4(rowp + (size_t)k * (HH * WW));
    }
    return valid;
}

__device__ __forceinline__ void sts_row(uint32_t slot, const float4* v,
                                        bool valid, int w, int l) {
    uint32_t h[8][2];
#pragma unroll
    for (int k = 0; k < 8; ++k) {
        h[k][0] = valid ? packh2(v[k].x, v[k].y) : 0u;
        h[k][1] = valid ? packh2(v[k].z, v[k].w) : 0u;
    }
#pragma unroll
    for (int i = 0; i < 4; ++i) {
        const int idx = i >> 1;
        const uint32_t sel = (i & 1) ? 0x7632u : 0x5410u;
        uint32_t r0 = __byte_perm(h[0][idx], h[1][idx], sel);
        uint32_t r1 = __byte_perm(h[2][idx], h[3][idx], sel);
        uint32_t r2 = __byte_perm(h[4][idx], h[5][idx], sel);
        uint32_t r3 = __byte_perm(h[6][idx], h[7][idx], sel);
        int pix = 4 * l + i + 1;          // interior px 1..128
        sts128(slot + pix * 128 + ((w ^ (pix & 7)) << 4), r0, r1, r2, r3);
    }
}

__global__ __launch_bounds__(256, 1)
void conv_kernel(const float* __restrict__ x, float* __restrict__ out) {
    extern __shared__ char sm[];
    const uint32_t base = smem_to_u32(sm);
    const int tid  = threadIdx.x;
    const int wid  = tid >> 5;
    const int lane = tid & 31;

    // Stage all 9 weight tiles (swizzle: chunk j of oc-row nr -> j^(nr&7))
    for (int k = tid; k < 4608; k += 256) {
        int q = k & 511;
        int nr = q >> 3, j = q & 7;
        cp16(base + (k >> 9) * 8192 + nr * 128 + ((j ^ (nr & 7)) << 4),
             reinterpret_cast<const char*>(g_wB) + (size_t)k * 16);
    }
    cp_commit();

    // Zero the entire A ring once (pad columns px0/px129 stay 0 forever)
    for (int i = tid; i < (8 * AROW_B) / 16; i += 256)
        sts128(base + A_OFF + i * 16, 0u, 0u, 0u, 0u);
    __syncthreads();

    // Contiguous tile chunk for this CTA
    const int lo = (int)(((long long)blockIdx.x * NTILES2) / NCTA);
    const int hi = (int)(((long long)(blockIdx.x + 1) * NTILES2) / NCTA);

    // Prologue: 4 rows of first tile into slots 0..3 (direct from x)
    {
        const int n0 = lo >> 6, y0 = (lo & 63) * 2;
#pragma unroll 1
        for (int r = 0; r < 4; ++r) {
            float4 v[8];
            bool ok = ldg_row(v, x, n0, y0 + r, wid, lane);
            sts_row(base + A_OFF + r * AROW_B, v, ok, wid, lane);
        }
    }
    cp_wait0();                      // B resident
    __syncthreads();                 // A prologue + B visible

    // Warp layout: rw = output row within pair, m0 = 32-pixel quadrant
    const int rw = wid >> 2;
    const int m0 = (wid & 3) * 32;
    const int a_pl = lane & 15, a_hk = lane >> 4;
    const int b_nl = (lane & 7) + ((lane >> 4) << 3);
    const int b_hk = (lane >> 3) & 1;

    // Per-thread bias registers: oc = nj*8 + (lane&3)*2 + {0,1}
    float bv[8][2];
#pragma unroll
    for (int nj = 0; nj < 8; ++nj) {
        bv[nj][0] = g_beff[nj * 8 + (lane & 3) * 2];
        bv[nj][1] = g_beff[nj * 8 + (lane & 3) * 2 + 1];
    }

    int pos = 0;
    for (int t = lo; t < hi; ++t) {
        const bool has_next = (t + 1 < hi);
        const int nn  = (t + 1) >> 6;
        const int y0n = ((t + 1) & 63) * 2;
        const bool adj = has_next && (nn == (t >> 6));
        const int pr0 = adj ? y0n + 2 : y0n;
        const int pr1 = pr0 + 1;

        float acc[2][8][4];
#pragma unroll
        for (int mi = 0; mi < 2; ++mi)
#pragma unroll
            for (int nj = 0; nj < 8; ++nj)
#pragma unroll
                for (int r = 0; r < 4; ++r) acc[mi][nj][r] = 0.0f;

        auto dy_body = [&](int dy) {
            const uint32_t arow = base + A_OFF +
                ((pos + rw + dy) & 7) * AROW_B;
#pragma unroll
            for (int dx = 0; dx < 3; ++dx) {
                const uint32_t btap = base + (dy * 3 + dx) * 8192;
#pragma unroll
                for (int kc = 0; kc < 4; ++kc) {
                    uint32_t a[2][4];
#pragma unroll
                    for (int mi = 0; mi < 2; ++mi) {
                        int pix = m0 + mi * 16 + a_pl + dx;
                        ldsm_x4(a[mi], arow + pix * 128 +
                                (((2 * kc + a_hk) ^ (pix & 7)) << 4));
                    }
#pragma unroll
                    for (int nj = 0; nj < 4; ++nj) {
                        uint32_t b[4];
                        int nb = nj * 16 + b_nl;
                        ldsm_x4(b, btap + nb * 128 +
                                (((2 * kc + b_hk) ^ (b_nl & 7)) << 4));
#pragma unroll
                        for (int mi = 0; mi < 2; ++mi) {
                            mma16816(acc[mi][nj * 2 + 0], a[mi], b + 0);
                            mma16816(acc[mi][nj * 2 + 1], a[mi], b + 2);
                        }
                    }
                }
            }
        };

        // Interleaved staging: LDG row0 -> dy0 -> STS row0 ->
        //                      LDG row1 -> dy1 -> STS row1 -> dy2
        {
            float4 va[8];
            bool oka = false;
            if (has_next) oka = ldg_row(va, x, nn, pr0, wid, lane);
            dy_body(0);
            if (has_next)
                sts_row(base + A_OFF + ((pos + 4) & 7) * AROW_B, va, oka, wid, lane);
        }
        {
            float4 vb[8];
            bool okb = false;
            if (has_next) okb = ldg_row(vb, x, nn, pr1, wid, lane);
            dy_body(1);
            if (has_next)
                sts_row(base + A_OFF + ((pos + 5) & 7) * AROW_B, vb, okb, wid, lane);
        }
        dy_body(2);

        // Direct epilogue: STG.32 from fragments, bias fused in registers
        {
            const int n = t >> 6, y = (t & 63) * 2 + rw;
            float* ob = out + (size_t)n * (64 * 16384) + (size_t)y * 128;
            const int pl = lane >> 2;
#pragma unroll
            for (int mi = 0; mi < 2; ++mi) {
                int pbase = m0 + mi * 16 + pl;
#pragma unroll
                for (int nj = 0; nj < 8; ++nj) {
                    float* p0 = ob + (size_t)(nj * 8 + (lane & 3) * 2) * 16384;
                    p0[pbase]             = acc[mi][nj][0] + bv[nj][0];
                    p0[16384 + pbase]     = acc[mi][nj][1] + bv[nj][1];
                    p0[pbase + 8]         = acc[mi][nj][2] + bv[nj][0];
                    p0[16384 + pbase + 8] = acc[mi][nj][3] + bv[nj][1];
                }
            }
        }

        // Image boundary: stage the remaining 2 rows of the new image
        if (has_next && !adj) {
#pragma unroll 1
            for (int r = 2; r < 4; ++r) {
                float4 v[8];
                bool ok = ldg_row(v, x, nn, y0n + r, wid, lane);
                sts_row(base + A_OFF + ((pos + 4 + r) & 7) * AROW_B, v, ok, wid, lane);
            }
        }

        __syncthreads();             // staged rows visible; ring reads done
        if (has_next) pos = (pos + (adj ? 2 : 4)) & 7;
    }
}

// ---------------------------------------------------------------------------
extern "C" void kernel_launch(void* const* d_in, const int* in_sizes, int n_in,
                              void* d_out, int out_size) {
    const float* x  = (const float*)d_in[0];
    const float* w  = (const float*)d_in[1];
    const float* b  = (const float*)d_in[2];
    const float* wc = (const float*)d_in[3];
    const float* bc = (const float*)d_in[4];
    const float* gt = (const float*)d_in[5];
    float* out = (float*)d_out;

    static bool attr_set = false;
    if (!attr_set) {
        cudaFuncSetAttribute(conv_kernel,
                             cudaFuncAttributeMaxDynamicSharedMemorySize, SMEM_CONV);
        attr_set = true;
    }

    prep_all_kernel<<<64, 256>>>(w, b, wc, bc, gt);
    conv_kernel<<<NCTA, 256, SMEM_CONV>>>(x, out);
}